// round 3
// baseline (speedup 1.0000x reference)
#include <cuda_runtime.h>
#include <cstdint>

// dendriticNet fused stepper, GB300 sm_103a.
//
// Structure:
//   kernel 1 (nudge): row means of tanh(s1), tanh(s2) -> __device__ scratch
//   kernel 2 (fused): per-CTA 128x128 output tile of one of the 5 outputs.
//     For that output it runs a concatenated-K tf32 GEMM over its 1..3 terms
//     (gain coefficient + tanh folded into A-staging), then the Euler epilogue.
//
// Graph-capture safe: two plain kernel launches, no allocs, no sync, no memcpy.
// Scratch = tiny __device__ arrays (2 * 32768 floats).

#define B_ROWS  32768
#define HDIM    256
#define BM      128
#define BN      128
#define BK      16
#define STRIDE  20          // smem row stride (floats): conflict-free frag loads
#define NTHREADS 256

// Folded constants (DT=0.1, GLK=0.1, GB=1.0, GA=0.8, GD=1.0, GSOM=0.8)
#define ALPHA_S   0.81f     // 1 - DT*(GLK+GB+GA)
#define ALPHA_S2  0.89f     // 1 - DT*(GLK+GB)
#define ALPHA_I   0.81f     // 1 - DT*(GLK+GD+GSOM)
#define C_B       0.10f     // DT*GB
#define C_A       0.08f     // DT*GA
#define C_D       0.10f     // DT*GD
#define C_SOM     0.08f     // DT*GSOM

__device__ float g_nudge0[B_ROWS];
__device__ float g_nudge1[B_ROWS];

__device__ __forceinline__ float to_tf32(float x) {
    uint32_t u;
    asm("cvt.rna.tf32.f32 %0, %1;" : "=r"(u) : "f"(x));
    return __uint_as_float(u);
}

__device__ __forceinline__ void mma_tf32(float c[4], const uint32_t a[4], const uint32_t b[2]) {
    asm volatile(
        "mma.sync.aligned.m16n8k8.row.col.f32.tf32.tf32.f32 "
        "{%0,%1,%2,%3}, {%4,%5,%6,%7}, {%8,%9}, {%0,%1,%2,%3};\n"
        : "+f"(c[0]), "+f"(c[1]), "+f"(c[2]), "+f"(c[3])
        : "r"(a[0]), "r"(a[1]), "r"(a[2]), "r"(a[3]),
          "r"(b[0]), "r"(b[1]));
}

// ---------------------------------------------------------------------------
// Kernel 1: nudge0[row] = mean_j tanh(s1[row,j]); nudge1 likewise for s2.
// One warp per row; 8 rows per 256-thread block.
// ---------------------------------------------------------------------------
__global__ void nudge_kernel(const float* __restrict__ s1,
                             const float* __restrict__ s2) {
    int warp = threadIdx.x >> 5;
    int lane = threadIdx.x & 31;
    int row  = blockIdx.x * 8 + warp;
    const float* p1 = s1 + (size_t)row * HDIM;
    const float* p2 = s2 + (size_t)row * HDIM;
    float a = 0.f, b = 0.f;
    #pragma unroll
    for (int j = lane; j < HDIM; j += 32) {
        a += tanhf(p1[j]);
        b += tanhf(p2[j]);
    }
    #pragma unroll
    for (int o = 16; o; o >>= 1) {
        a += __shfl_xor_sync(0xffffffffu, a, o);
        b += __shfl_xor_sync(0xffffffffu, b, o);
    }
    if (lane == 0) {
        g_nudge0[row] = a * (1.0f / HDIM);
        g_nudge1[row] = b * (1.0f / HDIM);
    }
}

// ---------------------------------------------------------------------------
// Kernel 2: fused GEMM + epilogue.
// bid -> (out_id in 0..4, col_tile in 0..1, row_tile in 0..255)
// 8 warps in 4(M) x 2(N); warp tile 32x64; mma m16n8k8 tf32.
// ---------------------------------------------------------------------------
__global__ __launch_bounds__(NTHREADS, 1)
void fused_kernel(const float* __restrict__ data,
                  const float* __restrict__ s0, const float* __restrict__ s1,
                  const float* __restrict__ s2, const float* __restrict__ i0,
                  const float* __restrict__ i1,
                  const float* __restrict__ wpf0, const float* __restrict__ wpf1,
                  const float* __restrict__ wpf2,
                  const float* __restrict__ wpb0, const float* __restrict__ wpb1,
                  const float* __restrict__ wip0, const float* __restrict__ wip1,
                  const float* __restrict__ wpi0, const float* __restrict__ wpi1,
                  float* __restrict__ out) {
    __shared__ float As[2][BM * STRIDE];
    __shared__ float Ws[2][BN * STRIDE];

    int bid      = blockIdx.x;
    int out_id   = bid % 5;
    int rem      = bid / 5;
    int col_tile = rem & 1;
    int row_tile = rem >> 1;
    int row0     = row_tile * BM;
    int col0     = col_tile * BN;

    const float* Ap[3];
    const float* Wp[3];
    float coef[3];
    int   nterms;
    float alpha;
    const float* ndg = nullptr;
    const float* st;

    switch (out_id) {
    case 0:
        nterms = 3; alpha = ALPHA_S; st = s0;
        Ap[0] = data; Wp[0] = wpf0; coef[0] = C_B;
        Ap[1] = i0;   Wp[1] = wpi0; coef[1] = C_A;
        Ap[2] = s1;   Wp[2] = wpb0; coef[2] = C_A;
        break;
    case 1:
        nterms = 3; alpha = ALPHA_S; st = s1;
        Ap[0] = s0;   Wp[0] = wpf1; coef[0] = C_B;
        Ap[1] = i1;   Wp[1] = wpi1; coef[1] = C_A;
        Ap[2] = s2;   Wp[2] = wpb1; coef[2] = C_A;
        break;
    case 2:
        nterms = 1; alpha = ALPHA_S2; st = s2;
        Ap[0] = s1;   Wp[0] = wpf2; coef[0] = C_B;
        break;
    case 3:
        nterms = 1; alpha = ALPHA_I; st = i0; ndg = g_nudge0;
        Ap[0] = s0;   Wp[0] = wip0; coef[0] = C_D;
        break;
    default:
        nterms = 1; alpha = ALPHA_I; st = i1; ndg = g_nudge1;
        Ap[0] = s1;   Wp[0] = wip1; coef[0] = C_D;
        break;
    }

    int tid  = threadIdx.x;
    int lane = tid & 31;
    int warp = tid >> 5;
    int m0   = (warp >> 1) * 32;   // warp M offset in tile
    int n0   = (warp & 1) * 64;    // warp N offset in tile
    int qr   = lane >> 2;          // 0..7
    int qc   = lane & 3;           // 0..3

    float acc[2][8][4];
    #pragma unroll
    for (int mt = 0; mt < 2; mt++)
        #pragma unroll
        for (int nt = 0; nt < 8; nt++)
            #pragma unroll
            for (int k = 0; k < 4; k++) acc[mt][nt][k] = 0.f;

    // staging layout: thread -> (row, 4-float column group)
    int sr = tid >> 2;            // 0..63 (two passes cover 128 rows)
    int sc = (tid & 3) * 4;       // 0,4,8,12

    const int CH_PER_TERM = HDIM / BK;          // 16
    const int NCH = nterms * CH_PER_TERM;

    float4 ra[2], rw[2];

    auto loadChunk = [&](int c) {
        int t  = c >> 4;                         // term index
        int k0 = (c & 15) * BK;
        const float* A = Ap[t];
        const float* W = Wp[t];
        #pragma unroll
        for (int i = 0; i < 2; i++) {
            int r = sr + 64 * i;
            ra[i] = *(const float4*)(A + (size_t)(row0 + r) * HDIM + k0 + sc);
            rw[i] = *(const float4*)(W + (size_t)(col0 + r) * HDIM + k0 + sc);
        }
    };

    auto storeChunk = [&](int buf, float cf) {
        #pragma unroll
        for (int i = 0; i < 2; i++) {
            int r = sr + 64 * i;
            float* a = &As[buf][r * STRIDE + sc];
            a[0] = to_tf32(cf * tanhf(ra[i].x));
            a[1] = to_tf32(cf * tanhf(ra[i].y));
            a[2] = to_tf32(cf * tanhf(ra[i].z));
            a[3] = to_tf32(cf * tanhf(ra[i].w));
            float* w = &Ws[buf][r * STRIDE + sc];
            w[0] = to_tf32(rw[i].x);
            w[1] = to_tf32(rw[i].y);
            w[2] = to_tf32(rw[i].z);
            w[3] = to_tf32(rw[i].w);
        }
    };

    auto compute = [&](int buf) {
        #pragma unroll
        for (int kk = 0; kk < BK; kk += 8) {
            uint32_t a[2][4], b[8][2];
            #pragma unroll
            for (int mt = 0; mt < 2; mt++) {
                const float* base = &As[buf][(m0 + mt * 16 + qr) * STRIDE + kk + qc];
                a[mt][0] = __float_as_uint(base[0]);
                a[mt][1] = __float_as_uint(base[8 * STRIDE]);
                a[mt][2] = __float_as_uint(base[4]);
                a[mt][3] = __float_as_uint(base[8 * STRIDE + 4]);
            }
            #pragma unroll
            for (int nt = 0; nt < 8; nt++) {
                const float* base = &Ws[buf][(n0 + nt * 8 + qr) * STRIDE + kk + qc];
                b[nt][0] = __float_as_uint(base[0]);
                b[nt][1] = __float_as_uint(base[4]);
            }
            #pragma unroll
            for (int mt = 0; mt < 2; mt++)
                #pragma unroll
                for (int nt = 0; nt < 8; nt++)
                    mma_tf32(acc[mt][nt], a[mt], b[nt]);
        }
    };

    // software-pipelined mainloop
    loadChunk(0);
    storeChunk(0, coef[0]);
    __syncthreads();
    for (int c = 0; c < NCH; c++) {
        if (c + 1 < NCH) loadChunk(c + 1);
        compute(c & 1);
        __syncthreads();
        if (c + 1 < NCH) {
            storeChunk((c + 1) & 1, coef[(c + 1) >> 4]);
            __syncthreads();
        }
    }

    // epilogue: out = alpha*state + acc (+ C_SOM * nudge[row] for i-outputs)
    size_t obase = (size_t)out_id * B_ROWS * HDIM;
    #pragma unroll
    for (int mt = 0; mt < 2; mt++) {
        #pragma unroll
        for (int half = 0; half < 2; half++) {
            int row = row0 + m0 + mt * 16 + qr + half * 8;
            float nv = ndg ? C_SOM * __ldg(&ndg[row]) : 0.f;
            const float* sp = st + (size_t)row * HDIM + col0 + n0;
            float*       op = out + obase + (size_t)row * HDIM + col0 + n0;
            #pragma unroll
            for (int nt = 0; nt < 8; nt++) {
                int cc = nt * 8 + 2 * qc;
                float2 sv = *(const float2*)(sp + cc);
                float v0 = alpha * sv.x + acc[mt][nt][half * 2 + 0] + nv;
                float v1 = alpha * sv.y + acc[mt][nt][half * 2 + 1] + nv;
                *(float2*)(op + cc) = make_float2(v0, v1);
            }
        }
    }
}

// ---------------------------------------------------------------------------
extern "C" void kernel_launch(void* const* d_in, const int* in_sizes, int n_in,
                              void* d_out, int out_size) {
    const float* data = (const float*)d_in[0];
    const float* s0   = (const float*)d_in[1];
    const float* s1   = (const float*)d_in[2];
    const float* s2   = (const float*)d_in[3];
    const float* i0   = (const float*)d_in[4];
    const float* i1   = (const float*)d_in[5];
    const float* wpf0 = (const float*)d_in[6];
    const float* wpf1 = (const float*)d_in[7];
    const float* wpf2 = (const float*)d_in[8];
    const float* wpb0 = (const float*)d_in[9];
    const float* wpb1 = (const float*)d_in[10];
    const float* wip0 = (const float*)d_in[11];
    const float* wip1 = (const float*)d_in[12];
    const float* wpi0 = (const float*)d_in[13];
    const float* wpi1 = (const float*)d_in[14];
    float* out = (float*)d_out;

    nudge_kernel<<<B_ROWS / 8, 256>>>(s1, s2);

    // 5 outputs * 256 row tiles * 2 col tiles = 2560 CTAs (outputs interleaved
    // via bid%5 so heavy 3-term CTAs mix with 1-term CTAs across waves).
    fused_kernel<<<2560, NTHREADS>>>(data, s0, s1, s2, i0, i1,
                                     wpf0, wpf1, wpf2, wpb0, wpb1,
                                     wip0, wip1, wpi0, wpi1, out);
}

// round 4
// speedup vs baseline: 1.8782x; 1.8782x over previous
#include <cuda_runtime.h>
#include <cstdint>

// dendriticNet fused stepper, GB300 sm_103a — Round 4.
//
//   kernel 1 (nudge): row means of tanh(s1), tanh(s2) -> __device__ scratch
//   kernel 2 (fused): per-CTA 128x256 (full-N) tile of one of 5 outputs.
//     Concatenated-K tf32 GEMM over 1..3 terms. Gain coef + tanh folded into
//     A staging (registers -> swizzled smem); B = raw weights via cp.async.cg
//     with a 4-buffer / depth-3 pipeline, ONE __syncthreads per BK=32 chunk.
//
// Graph-capture safe: kernel launches only, no allocs, scratch = __device__.

#define B_ROWS   32768
#define HDIM     256
#define BM       128
#define BN       256
#define BK       32
#define NTHREADS 512
#define NBUF     4

// Folded constants (DT=0.1, GLK=0.1, GB=1.0, GA=0.8, GD=1.0, GSOM=0.8)
#define ALPHA_S   0.81f
#define ALPHA_S2  0.89f
#define ALPHA_I   0.81f
#define C_B       0.10f
#define C_A       0.08f
#define C_D       0.10f
#define C_SOM     0.08f

#define A_BUF_FLOATS (BM * BK)          // 4096
#define B_BUF_FLOATS (BN * BK)          // 8192
#define SMEM_FLOATS  (NBUF * (A_BUF_FLOATS + B_BUF_FLOATS))   // 49152 = 192KB

__device__ float g_nudge0[B_ROWS];
__device__ float g_nudge1[B_ROWS];

__device__ __forceinline__ float to_tf32(float x) {
    uint32_t u;
    asm("cvt.rna.tf32.f32 %0, %1;" : "=r"(u) : "f"(x));
    return __uint_as_float(u);
}

__device__ __forceinline__ void mma_tf32(float c[4], const uint32_t a[4], const uint32_t b[2]) {
    asm volatile(
        "mma.sync.aligned.m16n8k8.row.col.f32.tf32.tf32.f32 "
        "{%0,%1,%2,%3}, {%4,%5,%6,%7}, {%8,%9}, {%0,%1,%2,%3};\n"
        : "+f"(c[0]), "+f"(c[1]), "+f"(c[2]), "+f"(c[3])
        : "r"(a[0]), "r"(a[1]), "r"(a[2]), "r"(a[3]),
          "r"(b[0]), "r"(b[1]));
}

__device__ __forceinline__ void cp_async16(uint32_t saddr, const void* gptr) {
    asm volatile("cp.async.cg.shared.global [%0], [%1], 16;\n" :: "r"(saddr), "l"(gptr));
}
__device__ __forceinline__ void cp_commit() {
    asm volatile("cp.async.commit_group;\n");
}
__device__ __forceinline__ void cp_wait2() {
    asm volatile("cp.async.wait_group 2;\n");
}

// ---------------------------------------------------------------------------
// Kernel 1: nudge row means.
// ---------------------------------------------------------------------------
__global__ void nudge_kernel(const float* __restrict__ s1,
                             const float* __restrict__ s2) {
    int warp = threadIdx.x >> 5;
    int lane = threadIdx.x & 31;
    int row  = blockIdx.x * 8 + warp;
    const float* p1 = s1 + (size_t)row * HDIM;
    const float* p2 = s2 + (size_t)row * HDIM;
    float a = 0.f, b = 0.f;
    #pragma unroll
    for (int j = lane; j < HDIM; j += 32) {
        a += tanhf(p1[j]);
        b += tanhf(p2[j]);
    }
    #pragma unroll
    for (int o = 16; o; o >>= 1) {
        a += __shfl_xor_sync(0xffffffffu, a, o);
        b += __shfl_xor_sync(0xffffffffu, b, o);
    }
    if (lane == 0) {
        g_nudge0[row] = a * (1.0f / HDIM);
        g_nudge1[row] = b * (1.0f / HDIM);
    }
}

// ---------------------------------------------------------------------------
// Kernel 2: fused GEMM + epilogue. 512 threads, 16 warps as 4(M) x 4(N),
// warp tile 32x64. Tile = 128 rows x 256 cols (full N).
// ---------------------------------------------------------------------------
__global__ __launch_bounds__(NTHREADS, 1)
void fused_kernel(const float* __restrict__ data,
                  const float* __restrict__ s0, const float* __restrict__ s1,
                  const float* __restrict__ s2, const float* __restrict__ i0,
                  const float* __restrict__ i1,
                  const float* __restrict__ wpf0, const float* __restrict__ wpf1,
                  const float* __restrict__ wpf2,
                  const float* __restrict__ wpb0, const float* __restrict__ wpb1,
                  const float* __restrict__ wip0, const float* __restrict__ wip1,
                  const float* __restrict__ wpi0, const float* __restrict__ wpi1,
                  float* __restrict__ out) {
    extern __shared__ float smem[];
    float* AsBase = smem;                              // NBUF * 4096
    float* BsBase = smem + NBUF * A_BUF_FLOATS;        // NBUF * 8192

    int bid    = blockIdx.x;
    int out_id = bid % 5;
    int row0   = (bid / 5) * BM;

    const float *A0, *A1 = nullptr, *A2 = nullptr;
    const float *W0, *W1 = nullptr, *W2 = nullptr;
    float cf0, cf1 = 0.f, cf2 = 0.f;
    int   nterms;
    float alpha;
    const float* ndg = nullptr;
    const float* st;

    switch (out_id) {
    case 0:
        nterms = 3; alpha = ALPHA_S; st = s0;
        A0 = data; W0 = wpf0; cf0 = C_B;
        A1 = i0;   W1 = wpi0; cf1 = C_A;
        A2 = s1;   W2 = wpb0; cf2 = C_A;
        break;
    case 1:
        nterms = 3; alpha = ALPHA_S; st = s1;
        A0 = s0;   W0 = wpf1; cf0 = C_B;
        A1 = i1;   W1 = wpi1; cf1 = C_A;
        A2 = s2;   W2 = wpb1; cf2 = C_A;
        break;
    case 2:
        nterms = 1; alpha = ALPHA_S2; st = s2;
        A0 = s1;   W0 = wpf2; cf0 = C_B;
        break;
    case 3:
        nterms = 1; alpha = ALPHA_I; st = i0; ndg = g_nudge0;
        A0 = s0;   W0 = wip0; cf0 = C_D;
        break;
    default:
        nterms = 1; alpha = ALPHA_I; st = i1; ndg = g_nudge1;
        A0 = s1;   W0 = wip1; cf0 = C_D;
        break;
    }

    const int NCH = nterms * (HDIM / BK);    // 8 or 24

    int tid  = threadIdx.x;
    int lane = tid & 31;
    int warp = tid >> 5;
    int m0   = (warp >> 2) * 32;
    int n0   = (warp & 3) * 64;
    int qr   = lane >> 3 << 1 | (lane >> 2 & 1);  // placeholder removed below
    qr       = lane >> 2;     // 0..7
    int qc   = lane & 3;      // 0..3

    // swizzled column offsets: co[i] = ((i ^ qr) * 4 + qc)  for seg index i
    int co[8];
    #pragma unroll
    for (int i = 0; i < 8; i++) co[i] = ((i ^ qr) << 2) | qc;

    float acc[2][8][4];
    #pragma unroll
    for (int mt = 0; mt < 2; mt++)
        #pragma unroll
        for (int nt = 0; nt < 8; nt++)
            #pragma unroll
            for (int k = 0; k < 4; k++) acc[mt][nt][k] = 0.f;

    // ---- A staging (registers, tanh+coef+tf32) ----
    // tasks: 128 rows x 8 segs(16B) = 1024, 2 per thread.
    int ar0 = tid >> 3;            // rows 0..63
    int as0 = tid & 7;
    int ar1 = (tid + NTHREADS) >> 3;   // rows 64..127
    int as1 = as0;
    float4 ra0, ra1;

    auto loadA = [&](int c) {
        int t  = c >> 3;
        int k0 = (c & 7) * BK;
        const float* A = (t == 0) ? A0 : ((t == 1) ? A1 : A2);
        ra0 = *(const float4*)(A + (size_t)(row0 + ar0) * HDIM + k0 + as0 * 4);
        ra1 = *(const float4*)(A + (size_t)(row0 + ar1) * HDIM + k0 + as1 * 4);
    };
    auto storeA = [&](int c) {
        int buf = c & (NBUF - 1);
        float cf = ((c >> 3) == 0) ? cf0 : (((c >> 3) == 1) ? cf1 : cf2);
        float* As = AsBase + buf * A_BUF_FLOATS;
        float4 v0, v1;
        v0.x = to_tf32(cf * tanhf(ra0.x)); v0.y = to_tf32(cf * tanhf(ra0.y));
        v0.z = to_tf32(cf * tanhf(ra0.z)); v0.w = to_tf32(cf * tanhf(ra0.w));
        v1.x = to_tf32(cf * tanhf(ra1.x)); v1.y = to_tf32(cf * tanhf(ra1.y));
        v1.z = to_tf32(cf * tanhf(ra1.z)); v1.w = to_tf32(cf * tanhf(ra1.w));
        *(float4*)(As + ar0 * BK + ((as0 ^ (ar0 & 7)) << 2)) = v0;
        *(float4*)(As + ar1 * BK + ((as1 ^ (ar1 & 7)) << 2)) = v1;
    };

    // ---- B staging: cp.async, 256 rows x 8 segs = 2048 tasks, 4 per thread ----
    auto loadB = [&](int c) {
        int buf = c & (NBUF - 1);
        int t   = c >> 3;
        int k0  = (c & 7) * BK;
        const float* W = (t == 0) ? W0 : ((t == 1) ? W1 : W2);
        float* Bs = BsBase + buf * B_BUF_FLOATS;
        #pragma unroll
        for (int j = 0; j < 4; j++) {
            int task = tid + j * NTHREADS;
            int row  = task >> 3;
            int seg  = task & 7;
            const void* g = (const void*)(W + (size_t)row * HDIM + k0 + seg * 4);
            uint32_t s = (uint32_t)__cvta_generic_to_shared(
                Bs + row * BK + ((seg ^ (row & 7)) << 2));
            cp_async16(s, g);
        }
    };

    auto compute = [&](int c) {
        int buf = c & (NBUF - 1);
        const float* As = AsBase + buf * A_BUF_FLOATS;
        const float* Bs = BsBase + buf * B_BUF_FLOATS;
        #pragma unroll
        for (int kk = 0; kk < BK; kk += 8) {
            int s4 = kk >> 2;
            uint32_t a[2][4], b[8][2];
            #pragma unroll
            for (int mt = 0; mt < 2; mt++) {
                const float* r0 = As + (m0 + mt * 16 + qr) * BK;
                const float* r1 = r0 + 8 * BK;
                a[mt][0] = __float_as_uint(r0[co[s4]]);
                a[mt][1] = __float_as_uint(r1[co[s4]]);
                a[mt][2] = __float_as_uint(r0[co[s4 + 1]]);
                a[mt][3] = __float_as_uint(r1[co[s4 + 1]]);
            }
            #pragma unroll
            for (int nt = 0; nt < 8; nt++) {
                const float* r = Bs + (n0 + nt * 8 + qr) * BK;
                b[nt][0] = __float_as_uint(r[co[s4]]);
                b[nt][1] = __float_as_uint(r[co[s4 + 1]]);
            }
            #pragma unroll
            for (int mt = 0; mt < 2; mt++)
                #pragma unroll
                for (int nt = 0; nt < 8; nt++)
                    mma_tf32(acc[mt][nt], a[mt], b[nt]);
        }
    };

    // ---- pipeline: depth-3 B prefetch, depth-2 A regs, 1 barrier / chunk ----
    loadB(0); cp_commit();
    loadB(1); cp_commit();
    loadB(2); cp_commit();
    loadA(0);
    storeA(0);
    loadA(1);
    cp_wait2();              // B chunk 0 done
    __syncthreads();         // A0 + B0 visible to all

    for (int c = 0; c < NCH; c++) {
        if (c + 1 < NCH) storeA(c + 1);     // buf (c+1)%4: compute(c-3) done+synced
        if (c + 2 < NCH) loadA(c + 2);
        if (c + 3 < NCH) loadB(c + 3);      // buf (c+3)%4 == (c-1)%4: done+synced
        cp_commit();                        // empty groups at tail are legal
        compute(c);
        cp_wait2();                         // B chunk c+1 done (this warp)
        __syncthreads();                    // chunk c+1 (A store + all B waits) visible
    }

    // ---- epilogue: out = alpha*state + acc (+ C_SOM*nudge for i-outputs) ----
    size_t obase = (size_t)out_id * B_ROWS * HDIM;
    #pragma unroll
    for (int mt = 0; mt < 2; mt++) {
        #pragma unroll
        for (int half = 0; half < 2; half++) {
            int row = row0 + m0 + mt * 16 + qr + half * 8;
            float nv = ndg ? C_SOM * __ldg(&ndg[row]) : 0.f;
            const float* sp = st + (size_t)row * HDIM + n0;
            float*       op = out + obase + (size_t)row * HDIM + n0;
            #pragma unroll
            for (int nt = 0; nt < 8; nt++) {
                int cc = nt * 8 + 2 * qc;
                float2 sv = *(const float2*)(sp + cc);
                float v0 = alpha * sv.x + acc[mt][nt][half * 2 + 0] + nv;
                float v1 = alpha * sv.y + acc[mt][nt][half * 2 + 1] + nv;
                *(float2*)(op + cc) = make_float2(v0, v1);
            }
        }
    }
}

// ---------------------------------------------------------------------------
extern "C" void kernel_launch(void* const* d_in, const int* in_sizes, int n_in,
                              void* d_out, int out_size) {
    const float* data = (const float*)d_in[0];
    const float* s0   = (const float*)d_in[1];
    const float* s1   = (const float*)d_in[2];
    const float* s2   = (const float*)d_in[3];
    const float* i0   = (const float*)d_in[4];
    const float* i1   = (const float*)d_in[5];
    const float* wpf0 = (const float*)d_in[6];
    const float* wpf1 = (const float*)d_in[7];
    const float* wpf2 = (const float*)d_in[8];
    const float* wpb0 = (const float*)d_in[9];
    const float* wpb1 = (const float*)d_in[10];
    const float* wip0 = (const float*)d_in[11];
    const float* wip1 = (const float*)d_in[12];
    const float* wpi0 = (const float*)d_in[13];
    const float* wpi1 = (const float*)d_in[14];
    float* out = (float*)d_out;

    static const int smem_bytes = SMEM_FLOATS * 4;   // 192 KB
    cudaFuncSetAttribute(fused_kernel,
                         cudaFuncAttributeMaxDynamicSharedMemorySize, smem_bytes);

    nudge_kernel<<<B_ROWS / 8, 256>>>(s1, s2);

    // 5 outputs * 256 row tiles = 1280 CTAs, outputs interleaved via bid%5.
    fused_kernel<<<1280, NTHREADS, smem_bytes>>>(data, s0, s1, s2, i0, i1,
                                                 wpf0, wpf1, wpf2, wpb0, wpb1,
                                                 wip0, wip1, wpi0, wpi1, out);
}

// round 6
// speedup vs baseline: 2.7843x; 1.4824x over previous
#include <cuda_runtime.h>
#include <cuda_fp16.h>
#include <cstdint>

// dendriticNet fused stepper, GB300 sm_103a — Round 6: fp16 mma.sync +
// fragment-packed operands.
//
//   kernel 0 (prep):  9 fp32 weight matrices -> fp16 in exact mma.sync
//                     m16n8k16 B-fragment order (__device__ scratch, 1.44MB).
//                     cp.async in the fused kernel is then an identity copy.
//   kernel 1 (nudge): row means of tanh(s1), tanh(s2) -> __device__ scratch.
//   kernel 2 (fused): per-CTA 128x256 tile of one of 5 outputs.
//                     Concatenated-K fp16 GEMM over 1..3 terms:
//                       A = coef*tanh(act), packed to A-fragment order in smem
//                       B = prepacked weights via cp.async (identity)
//                     Consumer does only LDS.128 + HMMA. R4's proven 4-buffer
//                     pipeline (cp.async depth 3, 1 barrier/chunk).
//
// Graph-capture safe: kernel launches only, no allocs, scratch = __device__.

#define B_ROWS   32768
#define HDIM     256
#define BM       128
#define BN       256
#define BK       32
#define NTHREADS 512
#define NBUF     4

// Packed tile sizes (bytes)
#define A_BYTES  8192            // 128 x 32 halves, A-fragment order
#define B_BYTES  20480           // 256 x 32 halves, B-fragment order, 80B/lane
#define W_PACK_BYTES (8 * B_BYTES)   // 8 K-chunks per weight
#define SMEM_BYTES (NBUF * (A_BYTES + B_BYTES))   // 114688

// Folded constants (DT=0.1, GLK=0.1, GB=1.0, GA=0.8, GD=1.0, GSOM=0.8)
#define ALPHA_S   0.81f
#define ALPHA_S2  0.89f
#define ALPHA_I   0.81f
#define C_B       0.10f
#define C_A       0.08f
#define C_D       0.10f
#define C_SOM     0.08f

__device__ __align__(16) unsigned char g_wpack[9][W_PACK_BYTES];
__device__ float g_nudge0[B_ROWS];
__device__ float g_nudge1[B_ROWS];

// ---------------------------------------------------------------------------
// helpers
// ---------------------------------------------------------------------------
__device__ __forceinline__ uint32_t smem_u32(const void* p) {
    uint32_t a;
    asm("{ .reg .u64 t; cvta.to.shared.u64 t, %1; cvt.u32.u64 %0, t; }" : "=r"(a) : "l"(p));
    return a;
}
__device__ __forceinline__ float fast_tanh(float x) {
    // tanh(x) = 1 - 2/(exp2(2x/ln2)+1); approx err ~1e-7 << fp16 quantum
    float e;
    asm("ex2.approx.f32 %0, %1;" : "=f"(e) : "f"(x * 2.8853900818f));
    float r;
    asm("rcp.approx.f32 %0, %1;" : "=f"(r) : "f"(e + 1.0f));
    return fmaf(-2.0f, r, 1.0f);
}
__device__ __forceinline__ void cp_async16(uint32_t saddr, const void* g) {
    asm volatile("cp.async.cg.shared.global [%0], [%1], 16;\n" :: "r"(saddr), "l"(g));
}
__device__ __forceinline__ void cp_commit() { asm volatile("cp.async.commit_group;\n"); }
__device__ __forceinline__ void cp_wait2()  { asm volatile("cp.async.wait_group 2;\n"); }

__device__ __forceinline__ void lds128(uint32_t* r, uint32_t a) {
    asm volatile("ld.shared.v4.b32 {%0,%1,%2,%3}, [%4];"
        : "=r"(r[0]), "=r"(r[1]), "=r"(r[2]), "=r"(r[3]) : "r"(a));
}
__device__ __forceinline__ void sts32(uint32_t a, uint32_t v) {
    asm volatile("st.shared.b32 [%0], %1;" :: "r"(a), "r"(v) : "memory");
}
__device__ __forceinline__ void mma_f16(float c[4], const uint32_t a[4], const uint32_t b[2]) {
    asm volatile(
        "mma.sync.aligned.m16n8k16.row.col.f32.f16.f16.f32 "
        "{%0,%1,%2,%3}, {%4,%5,%6,%7}, {%8,%9}, {%0,%1,%2,%3};\n"
        : "+f"(c[0]), "+f"(c[1]), "+f"(c[2]), "+f"(c[3])
        : "r"(a[0]), "r"(a[1]), "r"(a[2]), "r"(a[3]), "r"(b[0]), "r"(b[1]));
}
__device__ __forceinline__ uint32_t h2bits(float x, float y) {
    __half2 h = __floats2half2_rn(x, y);
    return *reinterpret_cast<uint32_t*>(&h);
}

// ---------------------------------------------------------------------------
// Kernel 0: pack 9 weight matrices into fp16 B-fragment order.
// Granule = half2 (n fixed, k even pair). 9 * 256 * 128 granules.
//
// Layout per weight: [chunk 8][ngroup 4 * kstep 2 -> rg][lane 32 (80B)][i*4]
//   i = nt*2 + khi, nt = (n&63)>>3, khi = (k&15)>=8
//   lane = (n&7)*4 + (((k&15)>>1)&3)
// ---------------------------------------------------------------------------
__global__ void prep_kernel(const float* __restrict__ wpf0, const float* __restrict__ wpi0,
                            const float* __restrict__ wpb0, const float* __restrict__ wpf1,
                            const float* __restrict__ wpi1, const float* __restrict__ wpb1,
                            const float* __restrict__ wpf2, const float* __restrict__ wip0,
                            const float* __restrict__ wip1) {
    const float* Ws[9] = {wpf0, wpi0, wpb0, wpf1, wpi1, wpb1, wpf2, wip0, wip1};
    int idx = blockIdx.x * blockDim.x + threadIdx.x;   // < 9*32768
    int w   = idx >> 15;
    int rem = idx & 32767;
    int n   = rem >> 7;
    int kp  = rem & 127;
    int k   = kp * 2;

    float2 v = *(const float2*)(Ws[w] + n * HDIM + k);
    uint32_t bits = h2bits(v.x, v.y);

    int chunk = k >> 5;
    int ck    = k & 31;
    int kstep = ck >> 4;
    int ww    = ck & 15;
    int tig   = (ww >> 1) & 3;
    int khi   = (ww >= 8) ? 1 : 0;
    int ng    = n >> 6;
    int nn    = n & 63;
    int nt    = nn >> 3;
    int qr    = nn & 7;
    int lane  = qr * 4 + tig;
    int i     = nt * 2 + khi;
    uint32_t off = (uint32_t)chunk * B_BYTES + (uint32_t)(ng * 2 + kstep) * 2560
                 + (uint32_t)lane * 80 + (uint32_t)i * 4;
    *(uint32_t*)(&g_wpack[w][off]) = bits;
}

// ---------------------------------------------------------------------------
// Kernel 1: nudge row means.
// ---------------------------------------------------------------------------
__global__ void nudge_kernel(const float* __restrict__ s1,
                             const float* __restrict__ s2) {
    int warp = threadIdx.x >> 5;
    int lane = threadIdx.x & 31;
    int row  = blockIdx.x * 8 + warp;
    const float4* p1 = (const float4*)(s1 + (size_t)row * HDIM);
    const float4* p2 = (const float4*)(s2 + (size_t)row * HDIM);
    float a = 0.f, b = 0.f;
    #pragma unroll
    for (int j = lane; j < HDIM / 4; j += 32) {
        float4 v = p1[j];
        a += fast_tanh(v.x) + fast_tanh(v.y) + fast_tanh(v.z) + fast_tanh(v.w);
        float4 u = p2[j];
        b += fast_tanh(u.x) + fast_tanh(u.y) + fast_tanh(u.z) + fast_tanh(u.w);
    }
    #pragma unroll
    for (int o = 16; o; o >>= 1) {
        a += __shfl_xor_sync(0xffffffffu, a, o);
        b += __shfl_xor_sync(0xffffffffu, b, o);
    }
    if (lane == 0) {
        g_nudge0[row] = a * (1.0f / HDIM);
        g_nudge1[row] = b * (1.0f / HDIM);
    }
}

// ---------------------------------------------------------------------------
// Kernel 2: fused fp16 GEMM + epilogue. 512 threads, 16 warps 4(M)x4(N),
// warp tile 32x64.
// ---------------------------------------------------------------------------
__global__ __launch_bounds__(NTHREADS, 1)
void fused_kernel(const float* __restrict__ data,
                  const float* __restrict__ s0, const float* __restrict__ s1,
                  const float* __restrict__ s2, const float* __restrict__ i0,
                  const float* __restrict__ i1,
                  float* __restrict__ out) {
    extern __shared__ float smem[];
    uint32_t aBase = smem_u32(smem);                 // NBUF * A_BYTES
    uint32_t bBase = aBase + NBUF * A_BYTES;         // NBUF * B_BYTES

    int bid    = blockIdx.x;
    int out_id = bid % 5;
    int row0   = (bid / 5) * BM;

    const float *A0, *A1 = nullptr, *A2 = nullptr;
    const unsigned char *P0, *P1 = nullptr, *P2 = nullptr;
    float cf0, cf1 = 0.f, cf2 = 0.f;
    int   nterms;
    float alpha;
    const float* ndg = nullptr;
    const float* st;

    switch (out_id) {
    case 0: nterms = 3; alpha = ALPHA_S;  st = s0;
            A0 = data; P0 = g_wpack[0]; cf0 = C_B;
            A1 = i0;   P1 = g_wpack[1]; cf1 = C_A;
            A2 = s1;   P2 = g_wpack[2]; cf2 = C_A;  break;
    case 1: nterms = 3; alpha = ALPHA_S;  st = s1;
            A0 = s0;   P0 = g_wpack[3]; cf0 = C_B;
            A1 = i1;   P1 = g_wpack[4]; cf1 = C_A;
            A2 = s2;   P2 = g_wpack[5]; cf2 = C_A;  break;
    case 2: nterms = 1; alpha = ALPHA_S2; st = s2;
            A0 = s1;   P0 = g_wpack[6]; cf0 = C_B;  break;
    case 3: nterms = 1; alpha = ALPHA_I;  st = i0; ndg = g_nudge0;
            A0 = s0;   P0 = g_wpack[7]; cf0 = C_D;  break;
    default:nterms = 1; alpha = ALPHA_I;  st = i1; ndg = g_nudge1;
            A0 = s1;   P0 = g_wpack[8]; cf0 = C_D;  break;
    }
    const int NCH = nterms * (HDIM / BK);   // 8 or 24

    int tid  = threadIdx.x;
    int lane = tid & 31;
    int warp = tid >> 5;
    int qr   = lane >> 2;
    int qc   = lane & 3;
    int mtb  = (warp >> 2) * 2;        // A m16-tile base (0,2,4,6)
    int ngrp = warp & 3;               // B n-group (64 cols)

    float acc[2][8][4];
    #pragma unroll
    for (int mt = 0; mt < 2; mt++)
        #pragma unroll
        for (int nt = 0; nt < 8; nt++)
            #pragma unroll
            for (int kx = 0; kx < 4; kx++) acc[mt][nt][kx] = 0.f;

    // ---- A staging: 1024 float4-tasks (128 rows x 8 segs), 2 per thread ----
    int ar0 = tid >> 3;        // rows 0..63
    int seg = tid & 7;         // float4 index within 32-float row-chunk
    int ar1 = ar0 + 64;        // rows 64..127

    // fragment-packed offset of granule (row r, chunk-k ckg even)
    auto aoff = [&](int r, int ckg) -> uint32_t {
        int kstep = ckg >> 4;
        int ww    = ckg & 15;
        int tig   = (ww >> 1) & 3;
        int khi   = (ww >= 8) ? 1 : 0;
        int gi    = (khi << 1) | ((r >> 3) & 1);
        int ln    = (r & 7) * 4 + tig;
        return (uint32_t)(((r >> 4) * 2 + kstep) * 512 + ln * 16 + gi * 4);
    };
    uint32_t ao00 = aoff(ar0, seg * 4);
    uint32_t ao01 = aoff(ar0, seg * 4 + 2);
    uint32_t ao10 = aoff(ar1, seg * 4);
    uint32_t ao11 = aoff(ar1, seg * 4 + 2);

    float4 ra0, ra1;

    auto loadA = [&](int c) {
        int t  = c >> 3;
        int k0 = (c & 7) * BK;
        const float* A = (t == 0) ? A0 : ((t == 1) ? A1 : A2);
        ra0 = *(const float4*)(A + (size_t)(row0 + ar0) * HDIM + k0 + seg * 4);
        ra1 = *(const float4*)(A + (size_t)(row0 + ar1) * HDIM + k0 + seg * 4);
    };
    auto storeA = [&](int c) {
        int t = c >> 3;
        float cf = (t == 0) ? cf0 : ((t == 1) ? cf1 : cf2);
        uint32_t base = aBase + (uint32_t)(c & (NBUF - 1)) * A_BYTES;
        sts32(base + ao00, h2bits(cf * fast_tanh(ra0.x), cf * fast_tanh(ra0.y)));
        sts32(base + ao01, h2bits(cf * fast_tanh(ra0.z), cf * fast_tanh(ra0.w)));
        sts32(base + ao10, h2bits(cf * fast_tanh(ra1.x), cf * fast_tanh(ra1.y)));
        sts32(base + ao11, h2bits(cf * fast_tanh(ra1.z), cf * fast_tanh(ra1.w)));
    };

    // ---- B staging: identity cp.async of prepacked weights (1280 x 16B) ----
    auto loadB = [&](int c) {
        int t = c >> 3;
        const unsigned char* src =
            ((t == 0) ? P0 : ((t == 1) ? P1 : P2)) + (size_t)(c & 7) * B_BYTES;
        uint32_t dst = bBase + (uint32_t)(c & (NBUF - 1)) * B_BYTES;
        for (int tsk = tid; tsk < B_BYTES / 16; tsk += NTHREADS)
            cp_async16(dst + (uint32_t)tsk * 16, src + (size_t)tsk * 16);
    };

    auto compute = [&](int c) {
        uint32_t aB = aBase + (uint32_t)(c & (NBUF - 1)) * A_BYTES;
        uint32_t bB = bBase + (uint32_t)(c & (NBUF - 1)) * B_BYTES;
        #pragma unroll
        for (int ks = 0; ks < 2; ks++) {
            uint32_t af[2][4], bf[16];
            lds128(af[0], aB + (uint32_t)(((mtb + 0) * 2 + ks) * 512 + lane * 16));
            lds128(af[1], aB + (uint32_t)(((mtb + 1) * 2 + ks) * 512 + lane * 16));
            uint32_t bb = bB + (uint32_t)((ngrp * 2 + ks) * 2560 + lane * 80);
            lds128(bf + 0,  bb);
            lds128(bf + 4,  bb + 16);
            lds128(bf + 8,  bb + 32);
            lds128(bf + 12, bb + 48);
            #pragma unroll
            for (int nt = 0; nt < 8; nt++) {
                mma_f16(acc[0][nt], af[0], bf + nt * 2);
                mma_f16(acc[1][nt], af[1], bf + nt * 2);
            }
        }
    };

    // ---- pipeline (identical structure to the passing R4 kernel) ----
    loadB(0); cp_commit();
    loadB(1); cp_commit();
    loadB(2); cp_commit();
    loadA(0);
    storeA(0);
    loadA(1);
    cp_wait2();              // B chunk 0 done
    __syncthreads();         // chunk 0 visible

    for (int c = 0; c < NCH; c++) {
        if (c + 1 < NCH) storeA(c + 1);     // buf (c+1)%4: compute(c-3) done+synced
        if (c + 2 < NCH) loadA(c + 2);
        if (c + 3 < NCH) loadB(c + 3);      // buf (c-1)%4: done+synced
        cp_commit();
        compute(c);
        cp_wait2();                         // B chunk c+1 done
        __syncthreads();                    // chunk c+1 visible
    }

    // ---- epilogue: out = alpha*state + acc (+ C_SOM*nudge for i-outputs) ----
    size_t obase = (size_t)out_id * B_ROWS * HDIM;
    int m0 = (warp >> 2) * 32;
    int n0 = ngrp * 64;
    #pragma unroll
    for (int mt = 0; mt < 2; mt++) {
        #pragma unroll
        for (int half = 0; half < 2; half++) {
            int row = row0 + m0 + mt * 16 + qr + half * 8;
            float nv = ndg ? C_SOM * __ldg(&ndg[row]) : 0.f;
            const float* sp = st + (size_t)row * HDIM + n0;
            float*       op = out + obase + (size_t)row * HDIM + n0;
            #pragma unroll
            for (int nt = 0; nt < 8; nt++) {
                int cc = nt * 8 + 2 * qc;
                float2 sv = *(const float2*)(sp + cc);
                float v0 = alpha * sv.x + acc[mt][nt][half * 2 + 0] + nv;
                float v1 = alpha * sv.y + acc[mt][nt][half * 2 + 1] + nv;
                *(float2*)(op + cc) = make_float2(v0, v1);
            }
        }
    }
}

// ---------------------------------------------------------------------------
extern "C" void kernel_launch(void* const* d_in, const int* in_sizes, int n_in,
                              void* d_out, int out_size) {
    const float* data = (const float*)d_in[0];
    const float* s0   = (const float*)d_in[1];
    const float* s1   = (const float*)d_in[2];
    const float* s2   = (const float*)d_in[3];
    const float* i0   = (const float*)d_in[4];
    const float* i1   = (const float*)d_in[5];
    const float* wpf0 = (const float*)d_in[6];
    const float* wpf1 = (const float*)d_in[7];
    const float* wpf2 = (const float*)d_in[8];
    const float* wpb0 = (const float*)d_in[9];
    const float* wpb1 = (const float*)d_in[10];
    const float* wip0 = (const float*)d_in[11];
    const float* wip1 = (const float*)d_in[12];
    const float* wpi0 = (const float*)d_in[13];
    const float* wpi1 = (const float*)d_in[14];
    float* out = (float*)d_out;

    cudaFuncSetAttribute(fused_kernel,
                         cudaFuncAttributeMaxDynamicSharedMemorySize, SMEM_BYTES);

    // weight order in g_wpack: wpf0, wpi0, wpb0, wpf1, wpi1, wpb1, wpf2, wip0, wip1
    prep_kernel<<<9 * 32768 / 256, 256>>>(wpf0, wpi0, wpb0, wpf1, wpi1, wpb1,
                                          wpf2, wip0, wip1);
    nudge_kernel<<<B_ROWS / 8, 256>>>(s1, s2);

    // 5 outputs x 256 row tiles; consecutive bids share rows -> L2 reuse.
    fused_kernel<<<1280, NTHREADS, SMEM_BYTES>>>(data, s0, s1, s2, i0, i1, out);
}

// round 7
// speedup vs baseline: 3.1484x; 1.1308x over previous
#include <cuda_runtime.h>
#include <cuda_fp16.h>
#include <cstdint>

// dendriticNet fused stepper, GB300 sm_103a — Round 7.
// R6 skeleton + (1) tanh.approx.f32 staging, (2) gain coefficients folded into
// the prepacked weights, (3) prep+nudge merged into one launch with 4
// granules/thread coalesced prep.
//
// Graph-capture safe: kernel launches only, no allocs, scratch = __device__.

#define B_ROWS   32768
#define HDIM     256
#define BM       128
#define BN       256
#define BK       32
#define NTHREADS 512
#define NBUF     4

// Packed tile sizes (bytes)
#define A_BYTES  8192            // 128 x 32 halves, A-fragment order
#define B_BYTES  20480           // 256 x 32 halves, B-fragment order, 80B/lane
#define W_PACK_BYTES (8 * B_BYTES)   // 8 K-chunks per weight
#define SMEM_BYTES (NBUF * (A_BYTES + B_BYTES))   // 114688

// Folded constants (DT=0.1, GLK=0.1, GB=1.0, GA=0.8, GD=1.0, GSOM=0.8)
#define ALPHA_S   0.81f
#define ALPHA_S2  0.89f
#define ALPHA_I   0.81f
#define C_B       0.10f
#define C_A       0.08f
#define C_D       0.10f
#define C_SOM     0.08f

#define PREP_W_BLOCKS 144        // 9*256*32 four-granule tasks / 512
#define PREP_N_BLOCKS 2048       // 32768 rows / 16 rows-per-block

__device__ __align__(16) unsigned char g_wpack[9][W_PACK_BYTES];
__device__ float g_nudge0[B_ROWS];
__device__ float g_nudge1[B_ROWS];

// ---------------------------------------------------------------------------
// helpers
// ---------------------------------------------------------------------------
__device__ __forceinline__ uint32_t smem_u32(const void* p) {
    uint32_t a;
    asm("{ .reg .u64 t; cvta.to.shared.u64 t, %1; cvt.u32.u64 %0, t; }" : "=r"(a) : "l"(p));
    return a;
}
__device__ __forceinline__ float tanh_hw(float x) {
    float y;
    asm("tanh.approx.f32 %0, %1;" : "=f"(y) : "f"(x));
    return y;
}
__device__ __forceinline__ void cp_async16(uint32_t saddr, const void* g) {
    asm volatile("cp.async.cg.shared.global [%0], [%1], 16;\n" :: "r"(saddr), "l"(g));
}
__device__ __forceinline__ void cp_commit() { asm volatile("cp.async.commit_group;\n"); }
__device__ __forceinline__ void cp_wait2()  { asm volatile("cp.async.wait_group 2;\n"); }

__device__ __forceinline__ void lds128(uint32_t* r, uint32_t a) {
    asm volatile("ld.shared.v4.b32 {%0,%1,%2,%3}, [%4];"
        : "=r"(r[0]), "=r"(r[1]), "=r"(r[2]), "=r"(r[3]) : "r"(a));
}
__device__ __forceinline__ void sts32(uint32_t a, uint32_t v) {
    asm volatile("st.shared.b32 [%0], %1;" :: "r"(a), "r"(v) : "memory");
}
__device__ __forceinline__ void mma_f16(float c[4], const uint32_t a[4], const uint32_t b[2]) {
    asm volatile(
        "mma.sync.aligned.m16n8k16.row.col.f32.f16.f16.f32 "
        "{%0,%1,%2,%3}, {%4,%5,%6,%7}, {%8,%9}, {%0,%1,%2,%3};\n"
        : "+f"(c[0]), "+f"(c[1]), "+f"(c[2]), "+f"(c[3])
        : "r"(a[0]), "r"(a[1]), "r"(a[2]), "r"(a[3]), "r"(b[0]), "r"(b[1]));
}
__device__ __forceinline__ uint32_t h2bits(float x, float y) {
    __half2 h = __floats2half2_rn(x, y);
    return *reinterpret_cast<uint32_t*>(&h);
}

// ---------------------------------------------------------------------------
// Kernel P: merged prep (weights -> coef*fp16, B-fragment order) + nudge.
//
// W job  (bid < 144): 4 consecutive k-granules per thread, coalesced 32B loads.
// N job  (bid >= 144): nudge row means of tanh(s1), tanh(s2). 16 rows/block.
// ---------------------------------------------------------------------------
__global__ __launch_bounds__(NTHREADS)
void prep_kernel(const float* __restrict__ wpf0, const float* __restrict__ wpi0,
                 const float* __restrict__ wpb0, const float* __restrict__ wpf1,
                 const float* __restrict__ wpi1, const float* __restrict__ wpb1,
                 const float* __restrict__ wpf2, const float* __restrict__ wip0,
                 const float* __restrict__ wip1,
                 const float* __restrict__ s1,  const float* __restrict__ s2) {
    int bid = blockIdx.x;
    if (bid < PREP_W_BLOCKS) {
        const float* Ws[9] = {wpf0, wpi0, wpb0, wpf1, wpi1, wpb1, wpf2, wip0, wip1};
        const float  Cs[9] = {C_B, C_A, C_A, C_B, C_A, C_A, C_B, C_D, C_D};
        int task = bid * NTHREADS + threadIdx.x;      // < 73728
        int w    = task >> 13;                        // 9
        int r    = task & 8191;
        int n    = r >> 5;                            // 256
        int j    = r & 31;                            // 32 four-granule groups
        int k0   = j * 8;                             // 8-aligned k base

        float cf = Cs[w];
        const float* src = Ws[w] + n * HDIM + k0;
        float4 v01 = *(const float4*)(src);
        float4 v23 = *(const float4*)(src + 4);
        uint32_t g0 = h2bits(cf * v01.x, cf * v01.y);
        uint32_t g1 = h2bits(cf * v01.z, cf * v01.w);
        uint32_t g2 = h2bits(cf * v23.x, cf * v23.y);
        uint32_t g3 = h2bits(cf * v23.z, cf * v23.w);

        int chunk = k0 >> 5;
        int ck    = k0 & 31;
        int kstep = ck >> 4;
        int khi   = ((ck & 15) >= 8) ? 1 : 0;         // constant over the 4 granules
        int ng    = n >> 6;
        int nn    = n & 63;
        int i     = (nn >> 3) * 2 + khi;
        int lane0 = (nn & 7) * 4;                     // tig = granule index 0..3
        uint32_t base = (uint32_t)chunk * B_BYTES + (uint32_t)(ng * 2 + kstep) * 2560
                      + (uint32_t)i * 4;
        unsigned char* dst = g_wpack[w];
        *(uint32_t*)(dst + base + (uint32_t)(lane0 + 0) * 80) = g0;
        *(uint32_t*)(dst + base + (uint32_t)(lane0 + 1) * 80) = g1;
        *(uint32_t*)(dst + base + (uint32_t)(lane0 + 2) * 80) = g2;
        *(uint32_t*)(dst + base + (uint32_t)(lane0 + 3) * 80) = g3;
    } else {
        int warp = threadIdx.x >> 5;
        int lane = threadIdx.x & 31;
        int row  = (bid - PREP_W_BLOCKS) * 16 + warp;
        const float4* p1 = (const float4*)(s1 + (size_t)row * HDIM);
        const float4* p2 = (const float4*)(s2 + (size_t)row * HDIM);
        float a = 0.f, b = 0.f;
        #pragma unroll
        for (int jj = lane; jj < HDIM / 4; jj += 32) {
            float4 v = p1[jj];
            a += tanh_hw(v.x) + tanh_hw(v.y) + tanh_hw(v.z) + tanh_hw(v.w);
            float4 u = p2[jj];
            b += tanh_hw(u.x) + tanh_hw(u.y) + tanh_hw(u.z) + tanh_hw(u.w);
        }
        #pragma unroll
        for (int o = 16; o; o >>= 1) {
            a += __shfl_xor_sync(0xffffffffu, a, o);
            b += __shfl_xor_sync(0xffffffffu, b, o);
        }
        if (lane == 0) {
            g_nudge0[row] = a * (1.0f / HDIM);
            g_nudge1[row] = b * (1.0f / HDIM);
        }
    }
}

// ---------------------------------------------------------------------------
// Kernel 2: fused fp16 GEMM + epilogue. 512 threads, 16 warps 4(M)x4(N),
// warp tile 32x64. (Identical structure to the passing R6 kernel; staging is
// now pure tanh.approx + pack, coefficients live in the weights.)
// ---------------------------------------------------------------------------
__global__ __launch_bounds__(NTHREADS, 1)
void fused_kernel(const float* __restrict__ data,
                  const float* __restrict__ s0, const float* __restrict__ s1,
                  const float* __restrict__ s2, const float* __restrict__ i0,
                  const float* __restrict__ i1,
                  float* __restrict__ out) {
    extern __shared__ float smem[];
    uint32_t aBase = smem_u32(smem);                 // NBUF * A_BYTES
    uint32_t bBase = aBase + NBUF * A_BYTES;         // NBUF * B_BYTES

    int bid    = blockIdx.x;
    int out_id = bid % 5;
    int row0   = (bid / 5) * BM;

    const float *A0, *A1 = nullptr, *A2 = nullptr;
    const unsigned char *P0, *P1 = nullptr, *P2 = nullptr;
    int   nterms;
    float alpha;
    const float* ndg = nullptr;
    const float* st;

    switch (out_id) {
    case 0: nterms = 3; alpha = ALPHA_S;  st = s0;
            A0 = data; P0 = g_wpack[0];
            A1 = i0;   P1 = g_wpack[1];
            A2 = s1;   P2 = g_wpack[2];  break;
    case 1: nterms = 3; alpha = ALPHA_S;  st = s1;
            A0 = s0;   P0 = g_wpack[3];
            A1 = i1;   P1 = g_wpack[4];
            A2 = s2;   P2 = g_wpack[5];  break;
    case 2: nterms = 1; alpha = ALPHA_S2; st = s2;
            A0 = s1;   P0 = g_wpack[6];  break;
    case 3: nterms = 1; alpha = ALPHA_I;  st = i0; ndg = g_nudge0;
            A0 = s0;   P0 = g_wpack[7];  break;
    default:nterms = 1; alpha = ALPHA_I;  st = i1; ndg = g_nudge1;
            A0 = s1;   P0 = g_wpack[8];  break;
    }
    const int NCH = nterms * (HDIM / BK);   // 8 or 24

    int tid  = threadIdx.x;
    int lane = tid & 31;
    int warp = tid >> 5;
    int qr   = lane >> 2;
    int qc   = lane & 3;
    int mtb  = (warp >> 2) * 2;        // A m16-tile base (0,2,4,6)
    int ngrp = warp & 3;               // B n-group (64 cols)

    float acc[2][8][4];
    #pragma unroll
    for (int mt = 0; mt < 2; mt++)
        #pragma unroll
        for (int nt = 0; nt < 8; nt++)
            #pragma unroll
            for (int kx = 0; kx < 4; kx++) acc[mt][nt][kx] = 0.f;

    // ---- A staging: 1024 float4-tasks (128 rows x 8 segs), 2 per thread ----
    int ar0 = tid >> 3;        // rows 0..63
    int seg = tid & 7;         // float4 index within 32-float row-chunk
    int ar1 = ar0 + 64;        // rows 64..127

    auto aoff = [&](int r, int ckg) -> uint32_t {
        int kstep = ckg >> 4;
        int ww    = ckg & 15;
        int tig   = (ww >> 1) & 3;
        int khi   = (ww >= 8) ? 1 : 0;
        int gi    = (khi << 1) | ((r >> 3) & 1);
        int ln    = (r & 7) * 4 + tig;
        return (uint32_t)(((r >> 4) * 2 + kstep) * 512 + ln * 16 + gi * 4);
    };
    uint32_t ao00 = aoff(ar0, seg * 4);
    uint32_t ao01 = aoff(ar0, seg * 4 + 2);
    uint32_t ao10 = aoff(ar1, seg * 4);
    uint32_t ao11 = aoff(ar1, seg * 4 + 2);

    float4 ra0, ra1;

    auto loadA = [&](int c) {
        int t  = c >> 3;
        int k0 = (c & 7) * BK;
        const float* A = (t == 0) ? A0 : ((t == 1) ? A1 : A2);
        ra0 = *(const float4*)(A + (size_t)(row0 + ar0) * HDIM + k0 + seg * 4);
        ra1 = *(const float4*)(A + (size_t)(row0 + ar1) * HDIM + k0 + seg * 4);
    };
    auto storeA = [&](int c) {
        uint32_t base = aBase + (uint32_t)(c & (NBUF - 1)) * A_BYTES;
        sts32(base + ao00, h2bits(tanh_hw(ra0.x), tanh_hw(ra0.y)));
        sts32(base + ao01, h2bits(tanh_hw(ra0.z), tanh_hw(ra0.w)));
        sts32(base + ao10, h2bits(tanh_hw(ra1.x), tanh_hw(ra1.y)));
        sts32(base + ao11, h2bits(tanh_hw(ra1.z), tanh_hw(ra1.w)));
    };

    // ---- B staging: identity cp.async of prepacked weights (1280 x 16B) ----
    auto loadB = [&](int c) {
        int t = c >> 3;
        const unsigned char* src =
            ((t == 0) ? P0 : ((t == 1) ? P1 : P2)) + (size_t)(c & 7) * B_BYTES;
        uint32_t dst = bBase + (uint32_t)(c & (NBUF - 1)) * B_BYTES;
        for (int tsk = tid; tsk < B_BYTES / 16; tsk += NTHREADS)
            cp_async16(dst + (uint32_t)tsk * 16, src + (size_t)tsk * 16);
    };

    auto compute = [&](int c) {
        uint32_t aB = aBase + (uint32_t)(c & (NBUF - 1)) * A_BYTES;
        uint32_t bB = bBase + (uint32_t)(c & (NBUF - 1)) * B_BYTES;
        #pragma unroll
        for (int ks = 0; ks < 2; ks++) {
            uint32_t af[2][4], bf[16];
            lds128(af[0], aB + (uint32_t)(((mtb + 0) * 2 + ks) * 512 + lane * 16));
            lds128(af[1], aB + (uint32_t)(((mtb + 1) * 2 + ks) * 512 + lane * 16));
            uint32_t bb = bB + (uint32_t)((ngrp * 2 + ks) * 2560 + lane * 80);
            lds128(bf + 0,  bb);
            lds128(bf + 4,  bb + 16);
            lds128(bf + 8,  bb + 32);
            lds128(bf + 12, bb + 48);
            #pragma unroll
            for (int nt = 0; nt < 8; nt++) {
                mma_f16(acc[0][nt], af[0], bf + nt * 2);
                mma_f16(acc[1][nt], af[1], bf + nt * 2);
            }
        }
    };

    // ---- pipeline (identical structure to R6) ----
    loadB(0); cp_commit();
    loadB(1); cp_commit();
    loadB(2); cp_commit();
    loadA(0);
    storeA(0);
    loadA(1);
    cp_wait2();              // B chunk 0 done
    __syncthreads();         // chunk 0 visible

    for (int c = 0; c < NCH; c++) {
        if (c + 1 < NCH) storeA(c + 1);     // buf (c+1)%4: compute(c-3) done+synced
        if (c + 2 < NCH) loadA(c + 2);
        if (c + 3 < NCH) loadB(c + 3);      // buf (c-1)%4: done+synced
        cp_commit();
        compute(c);
        cp_wait2();                         // B chunk c+1 done
        __syncthreads();                    // chunk c+1 visible
    }

    // ---- epilogue: out = alpha*state + acc (+ C_SOM*nudge for i-outputs) ----
    size_t obase = (size_t)out_id * B_ROWS * HDIM;
    int m0 = (warp >> 2) * 32;
    int n0 = ngrp * 64;
    #pragma unroll
    for (int mt = 0; mt < 2; mt++) {
        #pragma unroll
        for (int half = 0; half < 2; half++) {
            int row = row0 + m0 + mt * 16 + qr + half * 8;
            float nv = ndg ? C_SOM * __ldg(&ndg[row]) : 0.f;
            const float* sp = st + (size_t)row * HDIM + n0;
            float*       op = out + obase + (size_t)row * HDIM + n0;
            #pragma unroll
            for (int nt = 0; nt < 8; nt++) {
                int cc = nt * 8 + 2 * qc;
                float2 sv = *(const float2*)(sp + cc);
                float v0 = alpha * sv.x + acc[mt][nt][half * 2 + 0] + nv;
                float v1 = alpha * sv.y + acc[mt][nt][half * 2 + 1] + nv;
                *(float2*)(op + cc) = make_float2(v0, v1);
            }
        }
    }
}

// ---------------------------------------------------------------------------
extern "C" void kernel_launch(void* const* d_in, const int* in_sizes, int n_in,
                              void* d_out, int out_size) {
    const float* data = (const float*)d_in[0];
    const float* s0   = (const float*)d_in[1];
    const float* s1   = (const float*)d_in[2];
    const float* s2   = (const float*)d_in[3];
    const float* i0   = (const float*)d_in[4];
    const float* i1   = (const float*)d_in[5];
    const float* wpf0 = (const float*)d_in[6];
    const float* wpf1 = (const float*)d_in[7];
    const float* wpf2 = (const float*)d_in[8];
    const float* wpb0 = (const float*)d_in[9];
    const float* wpb1 = (const float*)d_in[10];
    const float* wip0 = (const float*)d_in[11];
    const float* wip1 = (const float*)d_in[12];
    const float* wpi0 = (const float*)d_in[13];
    const float* wpi1 = (const float*)d_in[14];
    float* out = (float*)d_out;

    cudaFuncSetAttribute(fused_kernel,
                         cudaFuncAttributeMaxDynamicSharedMemorySize, SMEM_BYTES);

    // merged prep (weight pack, coef folded) + nudge
    prep_kernel<<<PREP_W_BLOCKS + PREP_N_BLOCKS, NTHREADS>>>(
        wpf0, wpi0, wpb0, wpf1, wpi1, wpb1, wpf2, wip0, wip1, s1, s2);

    // 5 outputs x 256 row tiles; consecutive bids share rows -> L2 reuse.
    fused_kernel<<<1280, NTHREADS, SMEM_BYTES>>>(data, s0, s1, s2, i0, i1, out);
}